// round 14
// baseline (speedup 1.0000x reference)
#include <cuda_runtime.h>
#include <cuda_fp16.h>
#include <cstdint>

#define B_  64
#define T_  4096
#define E_  512
#define A_  256
#define CPB 64                     // CTAs per batch (T/64)

// ---------------------------------------------------------------------------
// scratch (allocation-free)
// ---------------------------------------------------------------------------
__device__ float g_dproj[B_ * A_];
__device__ float g_P[(size_t)B_ * CPB * E_];       // partial contexts, 8MB
__device__ float g_m[B_ * CPB];                    // per-CTA local max
__device__ float g_s[B_ * CPB];                    // per-CTA local expsum
// W in MMA-fragment order: idx = ((((wn*8+c)*4+ks)*4+n2)*32+lane)*4+reg (u32)
__device__ __align__(128) uint32_t g_Wfrag[65536]; // 256KB

// ---------------------------------------------------------------------------
// helpers
// ---------------------------------------------------------------------------
__device__ __forceinline__ uint32_t smem_u32(const void* p) {
    uint32_t a;
    asm("{ .reg .u64 t; cvta.to.shared.u64 t, %1; cvt.u32.u64 %0, t; }" : "=r"(a) : "l"(p));
    return a;
}
__device__ __forceinline__ uint32_t swz128(uint32_t o) { return o ^ ((o >> 3) & 0x70); }

// hardware tanh (MUFU.TANH)
__device__ __forceinline__ float tanh_hw(float x) {
    float y;
    asm("tanh.approx.f32 %0, %1;" : "=f"(y) : "f"(x));
    return y;
}

#define LDM4(r, a) \
    asm volatile("ldmatrix.sync.aligned.m8n8.x4.shared.b16 {%0,%1,%2,%3}, [%4];" \
        : "=r"((r)[0]), "=r"((r)[1]), "=r"((r)[2]), "=r"((r)[3]) : "r"(a))

#define CVT_F16X2(d, hi, lo) \
    asm("cvt.rn.f16x2.f32 %0, %1, %2;" : "=r"(d) : "f"(hi), "f"(lo))

__device__ __forceinline__ void mma_fp16(float* c, const uint32_t* a, const uint32_t* b) {
    asm volatile(
        "mma.sync.aligned.m16n8k16.row.col.f32.f16.f16.f32 "
        "{%0,%1,%2,%3}, {%4,%5,%6,%7}, {%8,%9}, {%0,%1,%2,%3};"
        : "+f"(c[0]), "+f"(c[1]), "+f"(c[2]), "+f"(c[3])
        : "r"(a[0]), "r"(a[1]), "r"(a[2]), "r"(a[3]), "r"(b[0]), "r"(b[1]));
}

// ---------------------------------------------------------------------------
// prep: W -> fragment-order fp16 table (two launches to keep scores at #4)
// reg j of lane l for (wn,c,ks,n2):
//   n = wn*64 + n2*16 + (j&1)*8 + (l>>2)
//   k = c*64 + ks*16 + (j>>1)*8 + 2*(l&3)      value = {W[k][n], W[k+1][n]}
// ---------------------------------------------------------------------------
__global__ void convert_wfrag_kernel(const float* __restrict__ W, int half) {
    int idx = half * 32768 + blockIdx.x * 256 + threadIdx.x;
    int reg  = idx & 3;
    int lane = (idx >> 2) & 31;
    int n2   = (idx >> 7) & 3;
    int ks   = (idx >> 9) & 3;
    int c    = (idx >> 11) & 7;
    int wn   = (idx >> 14) & 3;
    int n = wn * 64 + n2 * 16 + (reg & 1) * 8 + (lane >> 2);
    int k = c * 64 + ks * 16 + (reg >> 1) * 8 + 2 * (lane & 3);
    uint32_t p;
    CVT_F16X2(p, W[(k + 1) * A_ + n], W[k * A_ + n]);
    g_Wfrag[idx] = p;
}

__global__ void dproj_kernel(const float* __restrict__ dec,
                             const float* __restrict__ Wd,
                             const float* __restrict__ b_enc) {
    int b = blockIdx.x;
    int a = threadIdx.x;
    const float* d = dec + b * E_;
    float s = b_enc[a];
    #pragma unroll 8
    for (int e = 0; e < E_; ++e)
        s = fmaf(d[e], Wd[e * A_ + a], s);
    g_dproj[b * A_ + a] = s;
}

// ---------------------------------------------------------------------------
// K1: fused fp16 HMMA scores GEMM + local softmax + partial context.
// CTA: M=64 x N=256, K=512 in 8 chunks of 64. 8 warps (2M x 4N), warp 32x64.
// B operand: direct LDG.128 from fragment-order global (no smem for W at all)
// A operand: LDG fp32 -> cvt -> STS XH (double-buffered) -> LDSM, 1 sync/chunk.
// ---------------------------------------------------------------------------
#define KC       64
#define NCH      8
#define OFF_XH   0                      // 2 x 8KB fp16 X tiles
#define OFF_V    16384
#define OFF_DP   17408
#define OFF_RED  18432                  // 64 x 4 floats
#define OFF_U    19456                  // 64 floats
#define OFF_RW   19712                  // reduce scratch
#define SMEM_TOTAL 19840

__global__ void __launch_bounds__(256, 2)
scores_mma_kernel(const float* __restrict__ X,
                  const float* __restrict__ v_att,
                  const float* __restrict__ b_att,
                  float* __restrict__ weights)
{
    extern __shared__ char smem[];
    const uint32_t sb = smem_u32(smem);
    const int tid = threadIdx.x;
    const int lane = tid & 31, wid = tid >> 5;
    const int wm = wid >> 2, wn = wid & 3;      // 2 x 4 warp grid
    const int b = blockIdx.y;
    const int t0 = blockIdx.x * 64;
    const int cta = b * CPB + blockIdx.x;

    float* vs   = (float*)(smem + OFF_V);
    float* dps  = (float*)(smem + OFF_DP);
    float* red  = (float*)(smem + OFF_RED);
    float* usm  = (float*)(smem + OFF_U);
    float* rmax = (float*)(smem + OFF_RW);       // [8]
    float* rsum = rmax + 8;                      // [8]
    float* rsc  = rsum + 8;                      // [1]
    vs[tid]  = v_att[tid];
    dps[tid] = g_dproj[b * A_ + tid];

    const float* xrow = X + ((size_t)b * T_ + t0) * E_;

    float acc[2][8][4];
    #pragma unroll
    for (int mt = 0; mt < 2; ++mt)
        #pragma unroll
        for (int nt = 0; nt < 8; ++nt)
            #pragma unroll
            for (int e = 0; e < 4; ++e) acc[mt][nt][e] = 0.f;

    // hoisted, pre-swizzled A ldmatrix offsets (koff XORed in per use)
    const int rsel = lane & 15, chalf = lane >> 4;
    uint32_t aswz[2];
    #pragma unroll
    for (int mt = 0; mt < 2; ++mt)
        aswz[mt] = swz128((uint32_t)(((wm << 5) + (mt << 4) + rsel) << 7) + (chalf << 4));

    // X chunk: 64 rows x 64 fp32 = 1024 float4; thread handles 4 (it*256+tid)
    const float* xptr[4];
    uint32_t xsts[4];
    #pragma unroll
    for (int it = 0; it < 4; ++it) {
        int f = tid + (it << 8);
        int r = f >> 4, q = f & 15;
        xptr[it] = xrow + (size_t)r * E_ + (q << 2);
        xsts[it] = swz128((uint32_t)((r << 7) + (q << 3)));
    }

    // B fragment pointer: per chunk c, warp reads 512 uint4 at
    // g_Wfrag4 + (wn*8 + c)*512 + lane + (ks*4+n2)*32
    const uint4* wfr = (const uint4*)g_Wfrag + (size_t)wn * 4096 + lane;

    auto ldg_x = [&](float4* v) {
        #pragma unroll
        for (int it = 0; it < 4; ++it) {
            v[it] = *(const float4*)xptr[it];
            xptr[it] += KC;
        }
    };
    auto sts_x = [&](int c, const float4* v) {
        const uint32_t bufo = (uint32_t)(c & 1) << 13;   // 8KB
        #pragma unroll
        for (int it = 0; it < 4; ++it) {
            uint32_t p0, p1;
            CVT_F16X2(p0, v[it].y, v[it].x);
            CVT_F16X2(p1, v[it].w, v[it].z);
            *(uint2*)(smem + OFF_XH + bufo + xsts[it]) = make_uint2(p0, p1);
        }
    };

    // prologue: XH(0) stored; X(1) prefetched to regs
    float4 nx[4];
    {
        float4 v[4];
        ldg_x(v);            // chunk 0
        sts_x(0, v);
    }
    ldg_x(nx);               // chunk 1
    __syncthreads();                                     // XH(0) visible

    for (int c = 0; c < NCH; ++c) {
        const uint32_t xh = sb + OFF_XH + ((uint32_t)(c & 1) << 13);
        const uint4* wp = wfr + (size_t)c * 512;

        // store XH(c+1) from prefetched regs (other buffer — safe during MMA(c))
        if (c + 1 < NCH) sts_x(c + 1, nx);
        // prefetch X(c+2) into regs (no smem hazard)
        if (c + 2 < NCH) ldg_x(nx);

        #pragma unroll
        for (int ks = 0; ks < 4; ++ks) {
            const uint32_t koff = ks << 5;
            uint32_t A[2][4];
            uint4 Bq[4];
            // B fragments: 4 coalesced LDG.128 from L1-resident table
            #pragma unroll
            for (int n2 = 0; n2 < 4; ++n2)
                Bq[n2] = wp[(ks * 4 + n2) * 32];
            #pragma unroll
            for (int mt = 0; mt < 2; ++mt) LDM4(A[mt], xh + (aswz[mt] ^ koff));
            #pragma unroll
            for (int n2 = 0; n2 < 4; ++n2) {
                uint32_t be[2] = { Bq[n2].x, Bq[n2].z };
                uint32_t bo[2] = { Bq[n2].y, Bq[n2].w };
                #pragma unroll
                for (int mt = 0; mt < 2; ++mt) {
                    mma_fp16(acc[mt][n2 * 2],     A[mt], be);
                    mma_fp16(acc[mt][n2 * 2 + 1], A[mt], bo);
                }
            }
        }
        __syncthreads();     // XH(c) reads done; XH(c+1) visible
    }

    // ---- epilogue: tanh (MUFU) + v dot, reduce to per-row score ----
    const int g = lane >> 2, t = lane & 3;
    #pragma unroll
    for (int mt = 0; mt < 2; ++mt) {
        float pa = 0.f, pb = 0.f;
        #pragma unroll
        for (int nt = 0; nt < 8; ++nt) {
            int col = (wn << 6) + (nt << 3) + (t << 1);
            float v0 = vs[col], v1 = vs[col + 1];
            float d0 = dps[col], d1 = dps[col + 1];
            pa = fmaf(v0, tanh_hw(acc[mt][nt][0] + d0), pa);
            pa = fmaf(v1, tanh_hw(acc[mt][nt][1] + d1), pa);
            pb = fmaf(v0, tanh_hw(acc[mt][nt][2] + d0), pb);
            pb = fmaf(v1, tanh_hw(acc[mt][nt][3] + d1), pb);
        }
        pa += __shfl_xor_sync(0xffffffffu, pa, 1);
        pa += __shfl_xor_sync(0xffffffffu, pa, 2);
        pb += __shfl_xor_sync(0xffffffffu, pb, 1);
        pb += __shfl_xor_sync(0xffffffffu, pb, 2);
        if (t == 0) {
            int row = (wm << 5) + (mt << 4) + g;
            red[row * 4 + wn]       = pa;
            red[(row + 8) * 4 + wn] = pb;
        }
    }
    __syncthreads();

    // ---- local softmax over 64 rows ----
    float sval = -1e30f;
    if (tid < 64)
        sval = red[tid * 4] + red[tid * 4 + 1] + red[tid * 4 + 2] + red[tid * 4 + 3]
             + b_att[0];
    float wmx = sval;
    #pragma unroll
    for (int o = 16; o; o >>= 1) wmx = fmaxf(wmx, __shfl_xor_sync(0xffffffffu, wmx, o));
    if (lane == 0 && wid < 2) rmax[wid] = wmx;
    __syncthreads();
    if (tid == 0) rsc[0] = fmaxf(rmax[0], rmax[1]);
    __syncthreads();
    const float m_c = rsc[0];

    float u = (tid < 64) ? __expf(sval - m_c) : 0.f;
    if (tid < 64) {
        usm[tid] = u;
        weights[(size_t)b * T_ + t0 + tid] = u;    // unnormalized; fixed in combine
    }
    float wsum = u;
    #pragma unroll
    for (int o = 16; o; o >>= 1) wsum += __shfl_xor_sync(0xffffffffu, wsum, o);
    if (lane == 0 && wid < 2) rsum[wid] = wsum;
    __syncthreads();
    if (tid == 0) {
        g_m[cta] = m_c;
        g_s[cta] = rsum[0] + rsum[1];
    }
    __syncthreads();

    // ---- partial context: P_c[e] = sum_t u_t * X[t, e] ----
    #pragma unroll
    for (int half = 0; half < 2; ++half) {
        const float* xp = xrow + tid + (half << 8);
        float a0 = 0.f, a1 = 0.f, a2 = 0.f, a3 = 0.f;
        #pragma unroll 4
        for (int tt = 0; tt < 64; tt += 4) {
            a0 = fmaf(usm[tt + 0], xp[(size_t)(tt + 0) * E_], a0);
            a1 = fmaf(usm[tt + 1], xp[(size_t)(tt + 1) * E_], a1);
            a2 = fmaf(usm[tt + 2], xp[(size_t)(tt + 2) * E_], a2);
            a3 = fmaf(usm[tt + 3], xp[(size_t)(tt + 3) * E_], a3);
        }
        g_P[(size_t)cta * E_ + tid + (half << 8)] = (a0 + a1) + (a2 + a3);
    }
}

// ---------------------------------------------------------------------------
// K2: combine — cross-CTA softmax algebra, context, weight rescale.
// ---------------------------------------------------------------------------
__global__ void combine_kernel(float* __restrict__ ctx,
                               float* __restrict__ weights)
{
    const int b = blockIdx.x;
    const int tid = threadIdx.x;
    const int lane = tid & 31, wid = tid >> 5;
    __shared__ float alpha[CPB];
    __shared__ float wm2[2], ws2[2];

    float m = -1e30f, s = 0.f;
    if (tid < CPB) {
        m = g_m[b * CPB + tid];
        s = g_s[b * CPB + tid];
    }
    if (tid < CPB) {
        float M = m;
        #pragma unroll
        for (int o = 16; o; o >>= 1) M = fmaxf(M, __shfl_xor_sync(0xffffffffu, M, o));
        if (lane == 0) wm2[wid] = M;
    }
    __syncthreads();
    const float M = fmaxf(wm2[0], wm2[1]);
    float e = 0.f;
    if (tid < CPB) {
        e = __expf(m - M);
        float se = s * e;
        #pragma unroll
        for (int o = 16; o; o >>= 1) se += __shfl_xor_sync(0xffffffffu, se, o);
        if (lane == 0) ws2[wid] = se;
    }
    __syncthreads();
    if (tid < CPB) alpha[tid] = e / (ws2[0] + ws2[1]);
    __syncthreads();

    // context: e = tid
    {
        float a = 0.f;
        const float* P = g_P + (size_t)b * CPB * E_ + tid;
        #pragma unroll 8
        for (int c = 0; c < CPB; ++c)
            a = fmaf(P[(size_t)c * E_], alpha[c], a);
        ctx[(size_t)b * E_ + tid] = a;
    }
    // weights rescale
    {
        float* w = weights + (size_t)b * T_;
        #pragma unroll
        for (int i = tid; i < T_; i += 512)
            w[i] *= alpha[i >> 6];
    }
}

// ---------------------------------------------------------------------------
extern "C" void kernel_launch(void* const* d_in, const int* in_sizes, int n_in,
                              void* d_out, int out_size) {
    const float* X     = (const float*)d_in[0];
    const float* dec   = (const float*)d_in[1];
    const float* W_enc = (const float*)d_in[2];
    const float* b_enc = (const float*)d_in[3];
    const float* W_dec = (const float*)d_in[4];
    const float* v_att = (const float*)d_in[5];
    const float* b_att = (const float*)d_in[6];

    float* ctx     = (float*)d_out;
    float* weights = (float*)d_out + B_ * E_;

    cudaFuncSetAttribute(scores_mma_kernel,
                         cudaFuncAttributeMaxDynamicSharedMemorySize, SMEM_TOTAL);

    convert_wfrag_kernel<<<128, 256>>>(W_enc, 0);  // launch 1
    convert_wfrag_kernel<<<128, 256>>>(W_enc, 1);  // launch 2
    dproj_kernel<<<B_, A_>>>(dec, W_dec, b_enc);   // launch 3

    dim3 g1(T_ / 64, B_);
    scores_mma_kernel<<<g1, 256, SMEM_TOTAL>>>(X, v_att, b_att, weights);  // launch 4

    combine_kernel<<<B_, 512>>>(ctx, weights);
}

// round 15
// speedup vs baseline: 1.0264x; 1.0264x over previous
#include <cuda_runtime.h>
#include <cuda_fp16.h>
#include <cstdint>

#define B_  64
#define T_  4096
#define E_  512
#define A_  256
#define CPB 64                     // CTAs per batch (T/64)

// ---------------------------------------------------------------------------
// scratch (allocation-free)
// ---------------------------------------------------------------------------
__device__ float g_dproj[B_ * A_];
__device__ float g_P[(size_t)B_ * CPB * E_];       // partial contexts, 8MB
__device__ float g_m[B_ * CPB];                    // per-CTA local max
__device__ float g_s[B_ * CPB];                    // per-CTA local expsum
__device__ __align__(128) __half g_Wf[A_ * E_];    // [n][k] K-major fp16

// ---------------------------------------------------------------------------
// helpers
// ---------------------------------------------------------------------------
__device__ __forceinline__ uint32_t smem_u32(const void* p) {
    uint32_t a;
    asm("{ .reg .u64 t; cvta.to.shared.u64 t, %1; cvt.u32.u64 %0, t; }" : "=r"(a) : "l"(p));
    return a;
}
// 64B-row swizzle: bits[5:4] ^= bits[8:7]
__device__ __forceinline__ uint32_t swz64(uint32_t o) { return o ^ ((o >> 3) & 0x30); }

__device__ __forceinline__ float tanh_hw(float x) {
    float y;
    asm("tanh.approx.f32 %0, %1;" : "=f"(y) : "f"(x));
    return y;
}

#define CP_ASYNC16(dst, src) \
    asm volatile("cp.async.cg.shared.global [%0], [%1], 16;" :: "r"(dst), "l"(src) : "memory")
#define CP_COMMIT()  asm volatile("cp.async.commit_group;" ::: "memory")
#define CP_WAIT1()   asm volatile("cp.async.wait_group 1;" ::: "memory")
#define CP_WAIT0()   asm volatile("cp.async.wait_group 0;" ::: "memory")

#define LDM4(r, a) \
    asm volatile("ldmatrix.sync.aligned.m8n8.x4.shared.b16 {%0,%1,%2,%3}, [%4];" \
        : "=r"((r)[0]), "=r"((r)[1]), "=r"((r)[2]), "=r"((r)[3]) : "r"(a))

#define CVT_F16X2(d, hi, lo) \
    asm("cvt.rn.f16x2.f32 %0, %1, %2;" : "=r"(d) : "f"(hi), "f"(lo))

__device__ __forceinline__ void mma_fp16(float* c, const uint32_t* a, const uint32_t* b) {
    asm volatile(
        "mma.sync.aligned.m16n8k16.row.col.f32.f16.f16.f32 "
        "{%0,%1,%2,%3}, {%4,%5,%6,%7}, {%8,%9}, {%0,%1,%2,%3};"
        : "+f"(c[0]), "+f"(c[1]), "+f"(c[2]), "+f"(c[3])
        : "r"(a[0]), "r"(a[1]), "r"(a[2]), "r"(a[3]), "r"(b[0]), "r"(b[1]));
}

// ---------------------------------------------------------------------------
// small prep kernels
// ---------------------------------------------------------------------------
__global__ void convert_w_kernel(const float* __restrict__ W, int k0) {
    int k = k0 + blockIdx.x;
    int n = threadIdx.x;
    g_Wf[n * E_ + k] = __float2half_rn(W[k * A_ + n]);
}

__global__ void dproj_kernel(const float* __restrict__ dec,
                             const float* __restrict__ Wd,
                             const float* __restrict__ b_enc) {
    int b = blockIdx.x;
    int a = threadIdx.x;
    const float* d = dec + b * E_;
    float s = b_enc[a];
    #pragma unroll 8
    for (int e = 0; e < E_; ++e)
        s = fmaf(d[e], Wd[e * A_ + a], s);
    g_dproj[b * A_ + a] = s;
}

// ---------------------------------------------------------------------------
// K1: fused fp16 HMMA scores GEMM + local softmax + partial context.
// CTA: M=64 x N=256, K=512 in 16 chunks of 32. 8 warps (2M x 4N), warp 32x64.
// All 16 converted fp16 X chunks stay resident in smem (4KB+16pad each) so
// the context phase reads X from SMEM instead of re-reading global.
// W smem double-buffered (2x16KB). 1 sync/chunk. 2 CTAs/SM.
// ---------------------------------------------------------------------------
#define KC       32
#define NCH      16
#define CHSTR    4112                   // 4KB chunk + 16B bank-dealias pad
#define OFF_XH   0                      // 16 x CHSTR = 65792
#define OFF_W    65792                  // 2 x 16KB
#define OFF_V    98560
#define OFF_DP   99584
#define OFF_RED  100608                 // 64 x 4 floats
#define OFF_U    101632                 // 64 floats
#define OFF_RW   101888                 // reduce scratch
#define SMEM_TOTAL 102016

__global__ void __launch_bounds__(256, 2)
scores_mma_kernel(const float* __restrict__ X,
                  const float* __restrict__ v_att,
                  const float* __restrict__ b_att,
                  float* __restrict__ weights)
{
    extern __shared__ char smem[];
    const uint32_t sb = smem_u32(smem);
    const int tid = threadIdx.x;
    const int lane = tid & 31, wid = tid >> 5;
    const int wm = wid >> 2, wn = wid & 3;      // 2 x 4 warp grid
    const int b = blockIdx.y;
    const int t0 = blockIdx.x * 64;
    const int cta = b * CPB + blockIdx.x;

    float* vs   = (float*)(smem + OFF_V);
    float* dps  = (float*)(smem + OFF_DP);
    float* red  = (float*)(smem + OFF_RED);
    float* usm  = (float*)(smem + OFF_U);
    float* rmax = (float*)(smem + OFF_RW);       // [8]
    float* rsum = rmax + 8;                      // [8]
    float* rsc  = rsum + 8;                      // [1]
    vs[tid]  = v_att[tid];
    dps[tid] = g_dproj[b * A_ + tid];

    const float* xrow = X + ((size_t)b * T_ + t0) * E_;

    float acc[2][8][4];
    #pragma unroll
    for (int mt = 0; mt < 2; ++mt)
        #pragma unroll
        for (int nt = 0; nt < 8; ++nt)
            #pragma unroll
            for (int e = 0; e < 4; ++e) acc[mt][nt][e] = 0.f;

    // pre-swizzled ldmatrix offsets within a 64B-row tile (koff XORed per use)
    const int rsel = lane & 15, chalf = lane >> 4;
    uint32_t aswz[2], bswz[4];
    #pragma unroll
    for (int mt = 0; mt < 2; ++mt)
        aswz[mt] = swz64((uint32_t)(((wm << 5) + (mt << 4) + rsel) << 6) + (chalf << 4));
    #pragma unroll
    for (int n2 = 0; n2 < 4; ++n2)
        bswz[n2] = swz64((uint32_t)(((wn << 6) + (n2 << 4) + rsel) << 6) + (chalf << 4));

    // X chunk: 64 rows x 32 fp32 = 512 float4; thread handles 2 (it*256+tid)
    const float* xptr[2];
    uint32_t xsts[2];
    #pragma unroll
    for (int it = 0; it < 2; ++it) {
        int f = tid + (it << 8);
        int r = f >> 3, q = f & 7;
        xptr[it] = xrow + (size_t)r * E_ + (q << 2);
        xsts[it] = swz64((uint32_t)((r << 6) + (q << 3)));
    }
    // W cp.async: 256 rows x 32 fp16 = 1024 x 16B; thread handles 4
    const __half* wsrc = g_Wf;
    int woff[4];
    uint32_t wsts[4];
    #pragma unroll
    for (int it = 0; it < 4; ++it) {
        int i = tid + (it << 8);
        int r = i >> 2, q = i & 3;
        woff[it] = r * E_ + (q << 3);
        wsts[it] = sb + OFF_W + swz64((uint32_t)((r << 6) + (q << 4)));
    }

    auto ldg_x = [&](float4* v) {
        #pragma unroll
        for (int it = 0; it < 2; ++it) {
            v[it] = *(const float4*)xptr[it];
            xptr[it] += KC;
        }
    };
    auto sts_x = [&](int c, const float4* v) {
        char* buf = smem + OFF_XH + c * CHSTR;
        #pragma unroll
        for (int it = 0; it < 2; ++it) {
            uint32_t p0, p1;
            CVT_F16X2(p0, v[it].y, v[it].x);
            CVT_F16X2(p1, v[it].w, v[it].z);
            *(uint2*)(buf + xsts[it]) = make_uint2(p0, p1);
        }
    };
    auto load_w = [&](int c) {
        const uint32_t s14 = (uint32_t)(c & 1) << 14;
        #pragma unroll
        for (int it = 0; it < 4; ++it)
            CP_ASYNC16(wsts[it] + s14, wsrc + woff[it]);
        wsrc += KC;
        CP_COMMIT();
    };

    // prologue: W(0), W(1) async; XH(0) stored; X(1) prefetched to regs
    float4 nx[2];
    {
        float4 v[2];
        load_w(0);
        ldg_x(v);            // chunk 0
        load_w(1);
        sts_x(0, v);
    }
    ldg_x(nx);               // chunk 1
    __syncthreads();                                     // XH(0) visible

    for (int c = 0; c < NCH; ++c) {
        if (c + 1 < NCH) { CP_WAIT1(); }                 // W(c) done, W(c+1) in flight
        else             { CP_WAIT0(); }

        const uint32_t xh = sb + OFF_XH + (uint32_t)(c * CHSTR);
        const uint32_t wb = sb + OFF_W + ((uint32_t)(c & 1) << 14);

        if (c + 1 < NCH) sts_x(c + 1, nx);               // own buffer, no race
        if (c + 2 < NCH) ldg_x(nx);

        #pragma unroll
        for (int ks = 0; ks < 2; ++ks) {
            const uint32_t koff = ks << 5;
            uint32_t A[2][4], Bf[4][4];
            #pragma unroll
            for (int mt = 0; mt < 2; ++mt) LDM4(A[mt], xh + (aswz[mt] ^ koff));
            #pragma unroll
            for (int n2 = 0; n2 < 4; ++n2) LDM4(Bf[n2], wb + (bswz[n2] ^ koff));
            #pragma unroll
            for (int n2 = 0; n2 < 4; ++n2) {
                uint32_t be[2] = { Bf[n2][0], Bf[n2][2] };
                uint32_t bo[2] = { Bf[n2][1], Bf[n2][3] };
                #pragma unroll
                for (int mt = 0; mt < 2; ++mt) {
                    mma_fp16(acc[mt][n2 * 2],     A[mt], be);
                    mma_fp16(acc[mt][n2 * 2 + 1], A[mt], bo);
                }
            }
        }
        __syncthreads();     // Wbuf(c&1)/XH(c) reads done; XH(c+1) visible

        if (c + 2 < NCH) load_w(c + 2);                  // refill is post-barrier safe
    }

    // ---- epilogue: tanh (MUFU) + v dot, reduce to per-row score ----
    const int g = lane >> 2, t = lane & 3;
    #pragma unroll
    for (int mt = 0; mt < 2; ++mt) {
        float pa = 0.f, pb = 0.f;
        #pragma unroll
        for (int nt = 0; nt < 8; ++nt) {
            int col = (wn << 6) + (nt << 3) + (t << 1);
            float v0 = vs[col], v1 = vs[col + 1];
            float d0 = dps[col], d1 = dps[col + 1];
            pa = fmaf(v0, tanh_hw(acc[mt][nt][0] + d0), pa);
            pa = fmaf(v1, tanh_hw(acc[mt][nt][1] + d1), pa);
            pb = fmaf(v0, tanh_hw(acc[mt][nt][2] + d0), pb);
            pb = fmaf(v1, tanh_hw(acc[mt][nt][3] + d1), pb);
        }
        pa += __shfl_xor_sync(0xffffffffu, pa, 1);
        pa += __shfl_xor_sync(0xffffffffu, pa, 2);
        pb += __shfl_xor_sync(0xffffffffu, pb, 1);
        pb += __shfl_xor_sync(0xffffffffu, pb, 2);
        if (t == 0) {
            int row = (wm << 5) + (mt << 4) + g;
            red[row * 4 + wn]       = pa;
            red[(row + 8) * 4 + wn] = pb;
        }
    }
    __syncthreads();

    // ---- local softmax over 64 rows ----
    float sval = -1e30f;
    if (tid < 64)
        sval = red[tid * 4] + red[tid * 4 + 1] + red[tid * 4 + 2] + red[tid * 4 + 3]
             + b_att[0];
    float wmx = sval;
    #pragma unroll
    for (int o = 16; o; o >>= 1) wmx = fmaxf(wmx, __shfl_xor_sync(0xffffffffu, wmx, o));
    if (lane == 0 && wid < 2) rmax[wid] = wmx;
    __syncthreads();
    if (tid == 0) rsc[0] = fmaxf(rmax[0], rmax[1]);
    __syncthreads();
    const float m_c = rsc[0];

    float u = (tid < 64) ? __expf(sval - m_c) : 0.f;
    if (tid < 64) {
        usm[tid] = u;
        weights[(size_t)b * T_ + t0 + tid] = u;    // unnormalized; fixed in combine
    }
    float wsum = u;
    #pragma unroll
    for (int o = 16; o; o >>= 1) wsum += __shfl_xor_sync(0xffffffffu, wsum, o);
    if (lane == 0 && wid < 2) rsum[wid] = wsum;
    __syncthreads();
    if (tid == 0) {
        g_m[cta] = m_c;
        g_s[cta] = rsum[0] + rsum[1];
    }
    __syncthreads();

    // ---- partial context FROM SMEM: P_c[e] = sum_t u_t * XH[t, e] ----
    // thread handles one e-pair: chunk = tid>>4, pair q = tid&15 (e = 32c+2q)
    {
        const int cchunk = tid >> 4;
        const int q4 = (tid & 15) << 2;              // byte offset of pair in row
        const char* xb = smem + OFF_XH + cchunk * CHSTR;
        float P0 = 0.f, P1 = 0.f;
        #pragma unroll 8
        for (int tt = 0; tt < 64; ++tt) {
            uint32_t h = *(const uint32_t*)(xb + (tt << 6) + (q4 ^ ((tt & 6) << 3)));
            float2 xv = __half22float2(*(__half2*)&h);
            float ut = usm[tt];
            P0 = fmaf(ut, xv.x, P0);
            P1 = fmaf(ut, xv.y, P1);
        }
        int e = (cchunk << 5) + ((tid & 15) << 1);
        float* Pp = g_P + (size_t)cta * E_ + e;
        Pp[0] = P0;
        Pp[1] = P1;
    }
}

// ---------------------------------------------------------------------------
// K2: combine — cross-CTA softmax algebra, context, weight rescale.
// ---------------------------------------------------------------------------
__global__ void combine_kernel(float* __restrict__ ctx,
                               float* __restrict__ weights)
{
    const int b = blockIdx.x;
    const int tid = threadIdx.x;
    const int lane = tid & 31, wid = tid >> 5;
    __shared__ float alpha[CPB];
    __shared__ float wm2[2], ws2[2];

    float m = -1e30f, s = 0.f;
    if (tid < CPB) {
        m = g_m[b * CPB + tid];
        s = g_s[b * CPB + tid];
    }
    if (tid < CPB) {
        float M = m;
        #pragma unroll
        for (int o = 16; o; o >>= 1) M = fmaxf(M, __shfl_xor_sync(0xffffffffu, M, o));
        if (lane == 0) wm2[wid] = M;
    }
    __syncthreads();
    const float M = fmaxf(wm2[0], wm2[1]);
    float e = 0.f;
    if (tid < CPB) {
        e = __expf(m - M);
        float se = s * e;
        #pragma unroll
        for (int o = 16; o; o >>= 1) se += __shfl_xor_sync(0xffffffffu, se, o);
        if (lane == 0) ws2[wid] = se;
    }
    __syncthreads();
    if (tid < CPB) alpha[tid] = e / (ws2[0] + ws2[1]);
    __syncthreads();

    // context: e = tid
    {
        float a = 0.f;
        const float* P = g_P + (size_t)b * CPB * E_ + tid;
        #pragma unroll 8
        for (int c = 0; c < CPB; ++c)
            a = fmaf(P[(size_t)c * E_], alpha[c], a);
        ctx[(size_t)b * E_ + tid] = a;
    }
    // weights rescale
    {
        float* w = weights + (size_t)b * T_;
        #pragma unroll
        for (int i = tid; i < T_; i += 512)
            w[i] *= alpha[i >> 6];
    }
}

// ---------------------------------------------------------------------------
extern "C" void kernel_launch(void* const* d_in, const int* in_sizes, int n_in,
                              void* d_out, int out_size) {
    const float* X     = (const float*)d_in[0];
    const float* dec   = (const float*)d_in[1];
    const float* W_enc = (const float*)d_in[2];
    const float* b_enc = (const float*)d_in[3];
    const float* W_dec = (const float*)d_in[4];
    const float* v_att = (const float*)d_in[5];
    const float* b_att = (const float*)d_in[6];

    float* ctx     = (float*)d_out;
    float* weights = (float*)d_out + B_ * E_;

    cudaFuncSetAttribute(scores_mma_kernel,
                         cudaFuncAttributeMaxDynamicSharedMemorySize, SMEM_TOTAL);

    convert_w_kernel<<<256, 256>>>(W_enc, 0);     // launch 1
    convert_w_kernel<<<256, 256>>>(W_enc, 256);   // launch 2
    dproj_kernel<<<B_, A_>>>(dec, W_dec, b_enc);  // launch 3

    dim3 g1(T_ / 64, B_);
    scores_mma_kernel<<<g1, 256, SMEM_TOTAL>>>(X, v_att, b_att, weights);  // launch 4

    combine_kernel<<<B_, 512>>>(ctx, weights);
}

// round 16
// speedup vs baseline: 1.1080x; 1.0794x over previous
#include <cuda_runtime.h>
#include <cuda_fp16.h>
#include <cstdint>

#define B_  64
#define T_  4096
#define E_  512
#define A_  256
#define CPB 64                     // CTAs per batch (T/64)

// ---------------------------------------------------------------------------
// scratch (allocation-free)
// ---------------------------------------------------------------------------
__device__ float g_dproj[B_ * A_];
__device__ float g_P[(size_t)B_ * CPB * E_];       // partial contexts, 8MB
__device__ float g_m[B_ * CPB];                    // per-CTA local max
__device__ float g_s[B_ * CPB];                    // per-CTA local expsum
__device__ __align__(128) __half g_Wf[A_ * E_];    // [n][k] K-major fp16

// ---------------------------------------------------------------------------
// helpers
// ---------------------------------------------------------------------------
__device__ __forceinline__ uint32_t smem_u32(const void* p) {
    uint32_t a;
    asm("{ .reg .u64 t; cvta.to.shared.u64 t, %1; cvt.u32.u64 %0, t; }" : "=r"(a) : "l"(p));
    return a;
}
__device__ __forceinline__ uint32_t swz128(uint32_t o) { return o ^ ((o >> 3) & 0x70); }

__device__ __forceinline__ float tanh_hw(float x) {
    float y;
    asm("tanh.approx.f32 %0, %1;" : "=f"(y) : "f"(x));
    return y;
}

#define CP_ASYNC16(dst, src) \
    asm volatile("cp.async.cg.shared.global [%0], [%1], 16;" :: "r"(dst), "l"(src) : "memory")
#define CP_COMMIT()  asm volatile("cp.async.commit_group;" ::: "memory")
#define CP_WAIT1()   asm volatile("cp.async.wait_group 1;" ::: "memory")
#define CP_WAIT0()   asm volatile("cp.async.wait_group 0;" ::: "memory")

#define LDM4(r, a) \
    asm volatile("ldmatrix.sync.aligned.m8n8.x4.shared.b16 {%0,%1,%2,%3}, [%4];" \
        : "=r"((r)[0]), "=r"((r)[1]), "=r"((r)[2]), "=r"((r)[3]) : "r"(a))

#define CVT_F16X2(d, hi, lo) \
    asm("cvt.rn.f16x2.f32 %0, %1, %2;" : "=r"(d) : "f"(hi), "f"(lo))

__device__ __forceinline__ void mma_fp16(float* c, const uint32_t* a, const uint32_t* b) {
    asm volatile(
        "mma.sync.aligned.m16n8k16.row.col.f32.f16.f16.f32 "
        "{%0,%1,%2,%3}, {%4,%5,%6,%7}, {%8,%9}, {%0,%1,%2,%3};"
        : "+f"(c[0]), "+f"(c[1]), "+f"(c[2]), "+f"(c[3])
        : "r"(a[0]), "r"(a[1]), "r"(a[2]), "r"(a[3]), "r"(b[0]), "r"(b[1]));
}

// ---------------------------------------------------------------------------
// small prep kernels
// ---------------------------------------------------------------------------
__global__ void convert_w_kernel(const float* __restrict__ W) {
    int k = blockIdx.x;         // 512 blocks
    int n = threadIdx.x;        // 256
    g_Wf[n * E_ + k] = __float2half_rn(W[k * A_ + n]);
}

__global__ void dproj_kernel(const float* __restrict__ dec,
                             const float* __restrict__ Wd,
                             const float* __restrict__ b_enc) {
    int b = blockIdx.x;
    int a = threadIdx.x;
    const float* d = dec + b * E_;
    float s = b_enc[a];
    #pragma unroll 8
    for (int e = 0; e < E_; ++e)
        s = fmaf(d[e], Wd[e * A_ + a], s);
    g_dproj[b * A_ + a] = s;
}

// ---------------------------------------------------------------------------
// K1: fused fp16 HMMA scores GEMM + local softmax + partial context.
// CTA: M=64 x N=256, K=512 in 8 chunks of 64. 8 warps (2M x 4N), warp 32x64.
// (R13 structure — best measured: scores 242us.)
// ---------------------------------------------------------------------------
#define KC       64
#define NCH      8
#define OFF_XH   0                      // 2 x 8KB fp16 X tiles
#define OFF_W    16384                  // 2 x 32KB fp16 W
#define OFF_V    81920
#define OFF_DP   82944
#define OFF_RED  83968                  // 64 x 4 floats
#define OFF_U    85120                  // 64 floats
#define OFF_RW   85376                  // reduce scratch
#define SMEM_TOTAL 85504

__global__ void __launch_bounds__(256, 2)
scores_mma_kernel(const float* __restrict__ X,
                  const float* __restrict__ v_att,
                  const float* __restrict__ b_att,
                  float* __restrict__ weights)
{
    extern __shared__ char smem[];
    const uint32_t sb = smem_u32(smem);
    const int tid = threadIdx.x;
    const int lane = tid & 31, wid = tid >> 5;
    const int wm = wid >> 2, wn = wid & 3;      // 2 x 4 warp grid
    const int b = blockIdx.y;
    const int t0 = blockIdx.x * 64;
    const int cta = b * CPB + blockIdx.x;

    float* vs   = (float*)(smem + OFF_V);
    float* dps  = (float*)(smem + OFF_DP);
    float* red  = (float*)(smem + OFF_RED);
    float* usm  = (float*)(smem + OFF_U);
    float* rmax = (float*)(smem + OFF_RW);       // [8]
    float* rsum = rmax + 8;                      // [8]
    float* rsc  = rsum + 8;                      // [1]
    vs[tid]  = v_att[tid];
    dps[tid] = g_dproj[b * A_ + tid];

    const float* xrow = X + ((size_t)b * T_ + t0) * E_;

    float acc[2][8][4];
    #pragma unroll
    for (int mt = 0; mt < 2; ++mt)
        #pragma unroll
        for (int nt = 0; nt < 8; ++nt)
            #pragma unroll
            for (int e = 0; e < 4; ++e) acc[mt][nt][e] = 0.f;

    // hoisted, pre-swizzled ldmatrix offsets (koff XORed in per use)
    const int rsel = lane & 15, chalf = lane >> 4;
    uint32_t aswz[2], bswz[4];
    #pragma unroll
    for (int mt = 0; mt < 2; ++mt)
        aswz[mt] = swz128((uint32_t)(((wm << 5) + (mt << 4) + rsel) << 7) + (chalf << 4));
    #pragma unroll
    for (int n2 = 0; n2 < 4; ++n2)
        bswz[n2] = swz128((uint32_t)(((wn << 6) + (n2 << 4) + rsel) << 7) + (chalf << 4));

    // X chunk: 64 rows x 64 fp32 = 1024 float4; thread handles 4 (it*256+tid)
    const float* xptr[4];
    uint32_t xsts[4];
    #pragma unroll
    for (int it = 0; it < 4; ++it) {
        int f = tid + (it << 8);
        int r = f >> 4, q = f & 15;
        xptr[it] = xrow + (size_t)r * E_ + (q << 2);
        xsts[it] = swz128((uint32_t)((r << 7) + (q << 3)));
    }
    // W cp.async: fixed dst swizzles + src offsets; src base advances by KC.
    const __half* wsrc = g_Wf;
    int woff[8];
    uint32_t wsts[8];
    #pragma unroll
    for (int it = 0; it < 8; ++it) {
        int i = tid + (it << 8);
        int r = i >> 3, q = i & 7;
        woff[it] = r * E_ + (q << 3);
        wsts[it] = sb + OFF_W + swz128((uint32_t)((r << 7) + (q << 4)));
    }

    auto ldg_x = [&](float4* v) {
        #pragma unroll
        for (int it = 0; it < 4; ++it) {
            v[it] = *(const float4*)xptr[it];
            xptr[it] += KC;
        }
    };
    auto sts_x = [&](int c, const float4* v) {
        const uint32_t bufo = (uint32_t)(c & 1) << 13;   // 8KB
        #pragma unroll
        for (int it = 0; it < 4; ++it) {
            uint32_t p0, p1;
            CVT_F16X2(p0, v[it].y, v[it].x);
            CVT_F16X2(p1, v[it].w, v[it].z);
            *(uint2*)(smem + OFF_XH + bufo + xsts[it]) = make_uint2(p0, p1);
        }
    };
    auto load_w = [&](int c) {                           // W: 2048 x 16B, SW128
        const uint32_t s15 = (uint32_t)(c & 1) << 15;
        #pragma unroll
        for (int it = 0; it < 8; ++it)
            CP_ASYNC16(wsts[it] + s15, wsrc + woff[it]);
        wsrc += KC;                                      // next chunk
        CP_COMMIT();
    };

    // prologue: W(0), W(1) async; XH(0) stored; X(1) prefetched to regs
    float4 nx[4];
    {
        float4 v[4];
        load_w(0);
        ldg_x(v);            // chunk 0
        load_w(1);
        sts_x(0, v);
    }
    ldg_x(nx);               // chunk 1
    __syncthreads();                                     // XH(0) visible

    for (int c = 0; c < NCH; ++c) {
        if (c + 1 < NCH) { CP_WAIT1(); }                 // W(c) done, W(c+1) in flight
        else             { CP_WAIT0(); }

        const uint32_t xh = sb + OFF_XH + ((uint32_t)(c & 1) << 13);
        const uint32_t wb = sb + OFF_W + ((uint32_t)(c & 1) << 15);

        // store XH(c+1) from prefetched regs (other buffer — safe during MMA(c))
        if (c + 1 < NCH) sts_x(c + 1, nx);
        // prefetch X(c+2) into regs (no smem hazard)
        if (c + 2 < NCH) ldg_x(nx);

        #pragma unroll
        for (int ks = 0; ks < 4; ++ks) {
            const uint32_t koff = ks << 5;
            uint32_t A[2][4], Bf[4][4];
            #pragma unroll
            for (int mt = 0; mt < 2; ++mt) LDM4(A[mt], xh + (aswz[mt] ^ koff));
            #pragma unroll
            for (int n2 = 0; n2 < 4; ++n2) LDM4(Bf[n2], wb + (bswz[n2] ^ koff));
            #pragma unroll
            for (int n2 = 0; n2 < 4; ++n2) {
                uint32_t be[2] = { Bf[n2][0], Bf[n2][2] };
                uint32_t bo[2] = { Bf[n2][1], Bf[n2][3] };
                #pragma unroll
                for (int mt = 0; mt < 2; ++mt) {
                    mma_fp16(acc[mt][n2 * 2],     A[mt], be);
                    mma_fp16(acc[mt][n2 * 2 + 1], A[mt], bo);
                }
            }
        }
        __syncthreads();     // reads of Wbuf(c&1)/XH(c) done; XH(c+1) visible

        // safe to refill W buffer (c&1) with chunk c+2 now
        if (c + 2 < NCH) load_w(c + 2);
    }

    // ---- epilogue: tanh (MUFU) + v dot, reduce to per-row score ----
    const int g = lane >> 2, t = lane & 3;
    #pragma unroll
    for (int mt = 0; mt < 2; ++mt) {
        float pa = 0.f, pb = 0.f;
        #pragma unroll
        for (int nt = 0; nt < 8; ++nt) {
            int col = (wn << 6) + (nt << 3) + (t << 1);
            float v0 = vs[col], v1 = vs[col + 1];
            float d0 = dps[col], d1 = dps[col + 1];
            pa = fmaf(v0, tanh_hw(acc[mt][nt][0] + d0), pa);
            pa = fmaf(v1, tanh_hw(acc[mt][nt][1] + d1), pa);
            pb = fmaf(v0, tanh_hw(acc[mt][nt][2] + d0), pb);
            pb = fmaf(v1, tanh_hw(acc[mt][nt][3] + d1), pb);
        }
        pa += __shfl_xor_sync(0xffffffffu, pa, 1);
        pa += __shfl_xor_sync(0xffffffffu, pa, 2);
        pb += __shfl_xor_sync(0xffffffffu, pb, 1);
        pb += __shfl_xor_sync(0xffffffffu, pb, 2);
        if (t == 0) {
            int row = (wm << 5) + (mt << 4) + g;
            red[row * 4 + wn]       = pa;
            red[(row + 8) * 4 + wn] = pb;
        }
    }
    __syncthreads();

    // ---- local softmax over 64 rows ----
    float sval = -1e30f;
    if (tid < 64)
        sval = red[tid * 4] + red[tid * 4 + 1] + red[tid * 4 + 2] + red[tid * 4 + 3]
             + b_att[0];
    float wmx = sval;
    #pragma unroll
    for (int o = 16; o; o >>= 1) wmx = fmaxf(wmx, __shfl_xor_sync(0xffffffffu, wmx, o));
    if (lane == 0 && wid < 2) rmax[wid] = wmx;
    __syncthreads();
    if (tid == 0) rsc[0] = fmaxf(rmax[0], rmax[1]);
    __syncthreads();
    const float m_c = rsc[0];

    float u = (tid < 64) ? __expf(sval - m_c) : 0.f;
    if (tid < 64) {
        usm[tid] = u;
        weights[(size_t)b * T_ + t0 + tid] = u;    // unnormalized; fixed in combine
    }
    float wsum = u;
    #pragma unroll
    for (int o = 16; o; o >>= 1) wsum += __shfl_xor_sync(0xffffffffu, wsum, o);
    if (lane == 0 && wid < 2) rsum[wid] = wsum;
    __syncthreads();
    if (tid == 0) {
        g_m[cta] = m_c;
        g_s[cta] = rsum[0] + rsum[1];
    }
    __syncthreads();

    // ---- partial context: P_c[e] = sum_t u_t * X[t, e]  (8 MLP chains) ----
    #pragma unroll
    for (int half = 0; half < 2; ++half) {
        const float* xp = xrow + tid + (half << 8);
        float a[8] = {0,0,0,0,0,0,0,0};
        #pragma unroll 2
        for (int tt = 0; tt < 64; tt += 8) {
            #pragma unroll
            for (int u8 = 0; u8 < 8; ++u8)
                a[u8] = fmaf(usm[tt + u8], xp[(size_t)(tt + u8) * E_], a[u8]);
        }
        g_P[(size_t)cta * E_ + tid + (half << 8)] =
            ((a[0] + a[1]) + (a[2] + a[3])) + ((a[4] + a[5]) + (a[6] + a[7]));
    }
}

// ---------------------------------------------------------------------------
// K2: combine — cross-CTA softmax algebra, context, weight rescale.
// grid = B_, block = 1024; context reduction uses 8 MLP chains.
// ---------------------------------------------------------------------------
__global__ void combine_kernel(float* __restrict__ ctx,
                               float* __restrict__ weights)
{
    const int b = blockIdx.x;
    const int tid = threadIdx.x;
    const int lane = tid & 31, wid = tid >> 5;
    __shared__ float alpha[CPB];
    __shared__ float wm2[2], ws2[2];

    float m = -1e30f, s = 0.f;
    if (tid < CPB) {
        m = g_m[b * CPB + tid];
        s = g_s[b * CPB + tid];
    }
    if (tid < CPB) {
        float M = m;
        #pragma unroll
        for (int o = 16; o; o >>= 1) M = fmaxf(M, __shfl_xor_sync(0xffffffffu, M, o));
        if (lane == 0) wm2[wid] = M;
    }
    __syncthreads();
    const float M = fmaxf(wm2[0], wm2[1]);
    float e = 0.f;
    if (tid < CPB) {
        e = __expf(m - M);
        float se = s * e;
        #pragma unroll
        for (int o = 16; o; o >>= 1) se += __shfl_xor_sync(0xffffffffu, se, o);
        if (lane == 0) ws2[wid] = se;
    }
    __syncthreads();
    if (tid < CPB) alpha[tid] = e / (ws2[0] + ws2[1]);
    __syncthreads();

    // context: e = tid (first 512 threads), 8 independent chains
    if (tid < E_) {
        const float* P = g_P + (size_t)b * CPB * E_ + tid;
        float a[8] = {0,0,0,0,0,0,0,0};
        #pragma unroll 2
        for (int c = 0; c < CPB; c += 8) {
            #pragma unroll
            for (int u8 = 0; u8 < 8; ++u8)
                a[u8] = fmaf(P[(size_t)(c + u8) * E_], alpha[c + u8], a[u8]);
        }
        ctx[(size_t)b * E_ + tid] =
            ((a[0] + a[1]) + (a[2] + a[3])) + ((a[4] + a[5]) + (a[6] + a[7]));
    }
    // weights rescale: 1024 threads, 4 iters
    {
        float* w = weights + (size_t)b * T_;
        #pragma unroll
        for (int i = tid; i < T_; i += 1024)
            w[i] *= alpha[i >> 6];
    }
}

// ---------------------------------------------------------------------------
extern "C" void kernel_launch(void* const* d_in, const int* in_sizes, int n_in,
                              void* d_out, int out_size) {
    const float* X     = (const float*)d_in[0];
    const float* dec   = (const float*)d_in[1];
    const float* W_enc = (const float*)d_in[2];
    const float* b_enc = (const float*)d_in[3];
    const float* W_dec = (const float*)d_in[4];
    const float* v_att = (const float*)d_in[5];
    const float* b_att = (const float*)d_in[6];

    float* ctx     = (float*)d_out;
    float* weights = (float*)d_out + B_ * E_;

    cudaFuncSetAttribute(scores_mma_kernel,
                         cudaFuncAttributeMaxDynamicSharedMemorySize, SMEM_TOTAL);

    convert_w_kernel<<<512, 256>>>(W_enc);        // launch 1
    dproj_kernel<<<B_, A_>>>(dec, W_dec, b_enc);  // launch 2

    dim3 g1(T_ / 64, B_);
    scores_mma_kernel<<<g1, 256, SMEM_TOTAL>>>(X, v_att, b_att, weights);  // launch 3

    combine_kernel<<<B_, 1024>>>(ctx, weights);   // launch 4
}

// round 17
// speedup vs baseline: 1.1201x; 1.0109x over previous
#include <cuda_runtime.h>
#include <cuda_fp16.h>
#include <cstdint>

#define B_  64
#define T_  4096
#define E_  512
#define A_  256
#define CPB 64                     // CTAs per batch (T/64)

// ---------------------------------------------------------------------------
// scratch (allocation-free)
// ---------------------------------------------------------------------------
__device__ float g_dproj[B_ * A_];
__device__ float g_P[(size_t)B_ * CPB * E_];       // partial contexts, 8MB
__device__ float g_m[B_ * CPB];                    // per-CTA local max
__device__ float g_s[B_ * CPB];                    // per-CTA local expsum
__device__ __align__(128) __half g_Wf[A_ * E_];    // [n][k] K-major fp16

// ---------------------------------------------------------------------------
// helpers
// ---------------------------------------------------------------------------
__device__ __forceinline__ uint32_t smem_u32(const void* p) {
    uint32_t a;
    asm("{ .reg .u64 t; cvta.to.shared.u64 t, %1; cvt.u32.u64 %0, t; }" : "=r"(a) : "l"(p));
    return a;
}
__device__ __forceinline__ uint32_t swz128(uint32_t o) { return o ^ ((o >> 3) & 0x70); }

__device__ __forceinline__ float tanh_hw(float x) {
    float y;
    asm("tanh.approx.f32 %0, %1;" : "=f"(y) : "f"(x));
    return y;
}

#define CP_ASYNC16(dst, src) \
    asm volatile("cp.async.cg.shared.global [%0], [%1], 16;" :: "r"(dst), "l"(src) : "memory")
#define CP_COMMIT()  asm volatile("cp.async.commit_group;" ::: "memory")
#define CP_WAIT1()   asm volatile("cp.async.wait_group 1;" ::: "memory")
#define CP_WAIT0()   asm volatile("cp.async.wait_group 0;" ::: "memory")

#define LDM4(r, a) \
    asm volatile("ldmatrix.sync.aligned.m8n8.x4.shared.b16 {%0,%1,%2,%3}, [%4];" \
        : "=r"((r)[0]), "=r"((r)[1]), "=r"((r)[2]), "=r"((r)[3]) : "r"(a))

#define CVT_F16X2(d, hi, lo) \
    asm("cvt.rn.f16x2.f32 %0, %1, %2;" : "=r"(d) : "f"(hi), "f"(lo))

__device__ __forceinline__ void mma_fp16(float* c, const uint32_t* a, const uint32_t* b) {
    asm volatile(
        "mma.sync.aligned.m16n8k16.row.col.f32.f16.f16.f32 "
        "{%0,%1,%2,%3}, {%4,%5,%6,%7}, {%8,%9}, {%0,%1,%2,%3};"
        : "+f"(c[0]), "+f"(c[1]), "+f"(c[2]), "+f"(c[3])
        : "r"(a[0]), "r"(a[1]), "r"(a[2]), "r"(a[3]), "r"(b[0]), "r"(b[1]));
}

// ---------------------------------------------------------------------------
// prep: fused convert_w (blocks 0..511) + dproj (blocks 512..575)
// ---------------------------------------------------------------------------
__global__ void prep_kernel(const float* __restrict__ W,
                            const float* __restrict__ dec,
                            const float* __restrict__ Wd,
                            const float* __restrict__ b_enc) {
    if (blockIdx.x < 512) {
        int k = blockIdx.x;
        int n = threadIdx.x;
        g_Wf[n * E_ + k] = __float2half_rn(W[k * A_ + n]);
    } else {
        int b = blockIdx.x - 512;
        int a = threadIdx.x;
        const float* d = dec + b * E_;
        float s = b_enc[a];
        #pragma unroll 8
        for (int e = 0; e < E_; ++e)
            s = fmaf(d[e], Wd[e * A_ + a], s);
        g_dproj[b * A_ + a] = s;
    }
}

// ---------------------------------------------------------------------------
// K1: fused fp16 HMMA scores GEMM + local softmax + partial context.
// CTA: M=64 x N=256, K=512 in 8 chunks of 64. 8 warps (2M x 4N), warp 32x64.
// (R13/R16 structure — best measured.)
// ---------------------------------------------------------------------------
#define KC       64
#define NCH      8
#define OFF_XH   0                      // 2 x 8KB fp16 X tiles
#define OFF_W    16384                  // 2 x 32KB fp16 W
#define OFF_V    81920
#define OFF_DP   82944
#define OFF_RED  83968                  // 64 x 4 floats
#define OFF_U    85120                  // 64 floats
#define OFF_RW   85376                  // reduce scratch
#define SMEM_TOTAL 85504

__global__ void __launch_bounds__(256, 2)
scores_mma_kernel(const float* __restrict__ X,
                  const float* __restrict__ v_att,
                  const float* __restrict__ b_att,
                  float* __restrict__ weights)
{
    extern __shared__ char smem[];
    const uint32_t sb = smem_u32(smem);
    const int tid = threadIdx.x;
    const int lane = tid & 31, wid = tid >> 5;
    const int wm = wid >> 2, wn = wid & 3;      // 2 x 4 warp grid
    const int b = blockIdx.y;
    const int t0 = blockIdx.x * 64;
    const int cta = b * CPB + blockIdx.x;

    float* vs   = (float*)(smem + OFF_V);
    float* dps  = (float*)(smem + OFF_DP);
    float* red  = (float*)(smem + OFF_RED);
    float* usm  = (float*)(smem + OFF_U);
    float* rmax = (float*)(smem + OFF_RW);       // [8]
    float* rsum = rmax + 8;                      // [8]
    float* rsc  = rsum + 8;                      // [1]
    vs[tid]  = v_att[tid];
    dps[tid] = g_dproj[b * A_ + tid];

    const float* xrow = X + ((size_t)b * T_ + t0) * E_;

    float acc[2][8][4];
    #pragma unroll
    for (int mt = 0; mt < 2; ++mt)
        #pragma unroll
        for (int nt = 0; nt < 8; ++nt)
            #pragma unroll
            for (int e = 0; e < 4; ++e) acc[mt][nt][e] = 0.f;

    // hoisted, pre-swizzled ldmatrix offsets (koff XORed in per use)
    const int rsel = lane & 15, chalf = lane >> 4;
    uint32_t aswz[2], bswz[4];
    #pragma unroll
    for (int mt = 0; mt < 2; ++mt)
        aswz[mt] = swz128((uint32_t)(((wm << 5) + (mt << 4) + rsel) << 7) + (chalf << 4));
    #pragma unroll
    for (int n2 = 0; n2 < 4; ++n2)
        bswz[n2] = swz128((uint32_t)(((wn << 6) + (n2 << 4) + rsel) << 7) + (chalf << 4));

    // X chunk: 64 rows x 64 fp32 = 1024 float4; thread handles 4 (it*256+tid)
    const float* xptr[4];
    uint32_t xsts[4];
    #pragma unroll
    for (int it = 0; it < 4; ++it) {
        int f = tid + (it << 8);
        int r = f >> 4, q = f & 15;
        xptr[it] = xrow + (size_t)r * E_ + (q << 2);
        xsts[it] = swz128((uint32_t)((r << 7) + (q << 3)));
    }
    // W cp.async: fixed dst swizzles + src offsets; src base advances by KC.
    const __half* wsrc = g_Wf;
    int woff[8];
    uint32_t wsts[8];
    #pragma unroll
    for (int it = 0; it < 8; ++it) {
        int i = tid + (it << 8);
        int r = i >> 3, q = i & 7;
        woff[it] = r * E_ + (q << 3);
        wsts[it] = sb + OFF_W + swz128((uint32_t)((r << 7) + (q << 4)));
    }

    auto ldg_x = [&](float4* v) {
        #pragma unroll
        for (int it = 0; it < 4; ++it) {
            v[it] = *(const float4*)xptr[it];
            xptr[it] += KC;
        }
    };
    auto sts_x = [&](int c, const float4* v) {
        const uint32_t bufo = (uint32_t)(c & 1) << 13;   // 8KB
        #pragma unroll
        for (int it = 0; it < 4; ++it) {
            uint32_t p0, p1;
            CVT_F16X2(p0, v[it].y, v[it].x);
            CVT_F16X2(p1, v[it].w, v[it].z);
            *(uint2*)(smem + OFF_XH + bufo + xsts[it]) = make_uint2(p0, p1);
        }
    };
    auto load_w = [&](int c) {                           // W: 2048 x 16B, SW128
        const uint32_t s15 = (uint32_t)(c & 1) << 15;
        #pragma unroll
        for (int it = 0; it < 8; ++it)
            CP_ASYNC16(wsts[it] + s15, wsrc + woff[it]);
        wsrc += KC;                                      // next chunk
        CP_COMMIT();
    };

    // prologue: W(0), W(1) async; XH(0) stored; X(1) prefetched to regs
    float4 nx[4];
    {
        float4 v[4];
        load_w(0);
        ldg_x(v);            // chunk 0
        load_w(1);
        sts_x(0, v);
    }
    ldg_x(nx);               // chunk 1
    __syncthreads();                                     // XH(0) visible

    for (int c = 0; c < NCH; ++c) {
        // independent of W async group — issue before the wait
        if (c + 1 < NCH) sts_x(c + 1, nx);               // other XH buffer, safe
        if (c + 2 < NCH) ldg_x(nx);                      // regs only

        if (c + 1 < NCH) { CP_WAIT1(); }                 // W(c) done, W(c+1) in flight
        else             { CP_WAIT0(); }

        const uint32_t xh = sb + OFF_XH + ((uint32_t)(c & 1) << 13);
        const uint32_t wb = sb + OFF_W + ((uint32_t)(c & 1) << 15);

        #pragma unroll
        for (int ks = 0; ks < 4; ++ks) {
            const uint32_t koff = ks << 5;
            uint32_t A[2][4], Bf[4][4];
            #pragma unroll
            for (int mt = 0; mt < 2; ++mt) LDM4(A[mt], xh + (aswz[mt] ^ koff));
            #pragma unroll
            for (int n2 = 0; n2 < 4; ++n2) LDM4(Bf[n2], wb + (bswz[n2] ^ koff));
            #pragma unroll
            for (int n2 = 0; n2 < 4; ++n2) {
                uint32_t be[2] = { Bf[n2][0], Bf[n2][2] };
                uint32_t bo[2] = { Bf[n2][1], Bf[n2][3] };
                #pragma unroll
                for (int mt = 0; mt < 2; ++mt) {
                    mma_fp16(acc[mt][n2 * 2],     A[mt], be);
                    mma_fp16(acc[mt][n2 * 2 + 1], A[mt], bo);
                }
            }
        }
        __syncthreads();     // reads of Wbuf(c&1)/XH(c) done; XH(c+1) visible

        // safe to refill W buffer (c&1) with chunk c+2 now
        if (c + 2 < NCH) load_w(c + 2);
    }

    // ---- epilogue: tanh (MUFU) + v dot, reduce to per-row score ----
    const int g = lane >> 2, t = lane & 3;
    #pragma unroll
    for (int mt = 0; mt < 2; ++mt) {
        float pa = 0.f, pb = 0.f;
        #pragma unroll
        for (int nt = 0; nt < 8; ++nt) {
            int col = (wn << 6) + (nt << 3) + (t << 1);
            float v0 = vs[col], v1 = vs[col + 1];
            float d0 = dps[col], d1 = dps[col + 1];
            pa = fmaf(v0, tanh_hw(acc[mt][nt][0] + d0), pa);
            pa = fmaf(v1, tanh_hw(acc[mt][nt][1] + d1), pa);
            pb = fmaf(v0, tanh_hw(acc[mt][nt][2] + d0), pb);
            pb = fmaf(v1, tanh_hw(acc[mt][nt][3] + d1), pb);
        }
        pa += __shfl_xor_sync(0xffffffffu, pa, 1);
        pa += __shfl_xor_sync(0xffffffffu, pa, 2);
        pb += __shfl_xor_sync(0xffffffffu, pb, 1);
        pb += __shfl_xor_sync(0xffffffffu, pb, 2);
        if (t == 0) {
            int row = (wm << 5) + (mt << 4) + g;
            red[row * 4 + wn]       = pa;
            red[(row + 8) * 4 + wn] = pb;
        }
    }
    __syncthreads();

    // ---- local softmax over 64 rows ----
    float sval = -1e30f;
    if (tid < 64)
        sval = red[tid * 4] + red[tid * 4 + 1] + red[tid * 4 + 2] + red[tid * 4 + 3]
             + b_att[0];
    float wmx = sval;
    #pragma unroll
    for (int o = 16; o; o >>= 1) wmx = fmaxf(wmx, __shfl_xor_sync(0xffffffffu, wmx, o));
    if (lane == 0 && wid < 2) rmax[wid] = wmx;
    __syncthreads();
    if (tid == 0) rsc[0] = fmaxf(rmax[0], rmax[1]);
    __syncthreads();
    const float m_c = rsc[0];

    float u = (tid < 64) ? __expf(sval - m_c) : 0.f;
    if (tid < 64) {
        usm[tid] = u;
        weights[(size_t)b * T_ + t0 + tid] = u;    // unnormalized; fixed in combine
    }
    float wsum = u;
    #pragma unroll
    for (int o = 16; o; o >>= 1) wsum += __shfl_xor_sync(0xffffffffu, wsum, o);
    if (lane == 0 && wid < 2) rsum[wid] = wsum;
    __syncthreads();
    if (tid == 0) {
        g_m[cta] = m_c;
        g_s[cta] = rsum[0] + rsum[1];
    }
    __syncthreads();

    // ---- partial context: P_c[e] = sum_t u_t * X[t, e]  (8 MLP chains) ----
    #pragma unroll
    for (int half = 0; half < 2; ++half) {
        const float* xp = xrow + tid + (half << 8);
        float a[8] = {0,0,0,0,0,0,0,0};
        #pragma unroll 2
        for (int tt = 0; tt < 64; tt += 8) {
            #pragma unroll
            for (int u8 = 0; u8 < 8; ++u8)
                a[u8] = fmaf(usm[tt + u8], xp[(size_t)(tt + u8) * E_], a[u8]);
        }
        g_P[(size_t)cta * E_ + tid + (half << 8)] =
            ((a[0] + a[1]) + (a[2] + a[3])) + ((a[4] + a[5]) + (a[6] + a[7]));
    }
}

// ---------------------------------------------------------------------------
// K2: combine — parallelized. grid (B, 9): y<8 context slice, y==8 rescale.
// ---------------------------------------------------------------------------
__global__ void combine_kernel(float* __restrict__ ctx,
                               float* __restrict__ weights)
{
    const int b = blockIdx.x;
    const int part = blockIdx.y;
    const int tid = threadIdx.x;
    const int lane = tid & 31, wid = tid >> 5;
    __shared__ float alpha[CPB];
    __shared__ float wm2[2], ws2[2];

    // alpha (threads 0..63)
    if (tid < CPB) {
        float m = g_m[b * CPB + tid];
        float M = m;
        #pragma unroll
        for (int o = 16; o; o >>= 1) M = fmaxf(M, __shfl_xor_sync(0xffffffffu, M, o));
        if (lane == 0) wm2[wid] = M;
    }
    __syncthreads();
    if (tid < CPB) {
        const float M = fmaxf(wm2[0], wm2[1]);
        float e = __expf(g_m[b * CPB + tid] - M);
        float se = g_s[b * CPB + tid] * e;
        #pragma unroll
        for (int o = 16; o; o >>= 1) se += __shfl_xor_sync(0xffffffffu, se, o);
        if (lane == 0) ws2[wid] = se;
        alpha[tid] = e;                       // scale applied after sum known
    }
    __syncthreads();
    if (tid < CPB) alpha[tid] /= (ws2[0] + ws2[1]);
    __syncthreads();

    if (part < 8) {
        // context slice: e in [part*64, part*64+64), 4 threads per e
        const int e  = (part << 6) + (tid >> 2);
        const int cq = tid & 3;
        const int c0 = cq << 4;
        const float* P = g_P + ((size_t)b * CPB) * E_ + e;
        float a[4] = {0.f, 0.f, 0.f, 0.f};
        #pragma unroll
        for (int j = 0; j < 16; j += 4) {
            #pragma unroll
            for (int u4 = 0; u4 < 4; ++u4)
                a[u4] = fmaf(P[(size_t)(c0 + j + u4) * E_], alpha[c0 + j + u4], a[u4]);
        }
        float s = (a[0] + a[1]) + (a[2] + a[3]);
        s += __shfl_xor_sync(0xffffffffu, s, 1);
        s += __shfl_xor_sync(0xffffffffu, s, 2);
        if (cq == 0) ctx[(size_t)b * E_ + e] = s;
    } else {
        // weights rescale
        float* w = weights + (size_t)b * T_;
        #pragma unroll
        for (int i = tid; i < T_; i += 256)
            w[i] *= alpha[i >> 6];
    }
}

// ---------------------------------------------------------------------------
extern "C" void kernel_launch(void* const* d_in, const int* in_sizes, int n_in,
                              void* d_out, int out_size) {
    const float* X     = (const float*)d_in[0];
    const float* dec   = (const float*)d_in[1];
    const float* W_enc = (const float*)d_in[2];
    const float* b_enc = (const float*)d_in[3];
    const float* W_dec = (const float*)d_in[4];
    const float* v_att = (const float*)d_in[5];
    const float* b_att = (const float*)d_in[6];

    float* ctx     = (float*)d_out;
    float* weights = (float*)d_out + B_ * E_;

    cudaFuncSetAttribute(scores_mma_kernel,
                         cudaFuncAttributeMaxDynamicSharedMemorySize, SMEM_TOTAL);

    prep_kernel<<<576, 256>>>(W_enc, dec, W_dec, b_enc);  // launch 1

    dim3 g1(T_ / 64, B_);
    scores_mma_kernel<<<g1, 256, SMEM_TOTAL>>>(X, v_att, b_att, weights);  // launch 2

    dim3 g2(B_, 9);
    combine_kernel<<<g2, 256>>>(ctx, weights);            // launch 3
}